// round 14
// baseline (speedup 1.0000x reference)
#include <cuda_runtime.h>

static constexpr int Bn   = 128;
static constexpr int Nn   = 256;
static constexpr int SMAX = 300;

typedef unsigned long long u64;

__device__ float    g_partials[2 * Bn];  // [0..Bn) pair, [Bn..2Bn) setsize
__device__ unsigned g_count = 0;

__device__ __forceinline__ float fsqrt_ap(float x) {
    float r;
    asm("sqrt.approx.f32 %0, %1;" : "=f"(r) : "f"(x));
    return r;
}
// Warp-wide min for non-negative floats (u32 ordering == float ordering;
// NaN bit patterns are huge, so they lose the min — desired).
__device__ __forceinline__ float warp_min_nonneg(float x) {
    unsigned u = __float_as_uint(x), r;
    asm("redux.sync.min.u32 %0, %1, 0xffffffff;" : "=r"(r) : "r"(u));
    return __uint_as_float(r);
}
// ---- f32x2 packed helpers (Blackwell) ----
__device__ __forceinline__ u64 pack2(float lo, float hi) {
    u64 d;
    asm("mov.b64 %0, {%1, %2};" : "=l"(d) : "f"(lo), "f"(hi));
    return d;
}
__device__ __forceinline__ void unpack2(float& lo, float& hi, u64 v) {
    asm("mov.b64 {%0, %1}, %2;" : "=f"(lo), "=f"(hi) : "l"(v));
}
__device__ __forceinline__ u64 fma2(u64 a, u64 b, u64 c) {
    u64 d;
    asm("fma.rn.f32x2 %0, %1, %2, %3;" : "=l"(d) : "l"(a), "l"(b), "l"(c));
    return d;
}
__device__ __forceinline__ u64 add2(u64 a, u64 b) {
    u64 d;
    asm("add.rn.f32x2 %0, %1, %2;" : "=l"(d) : "l"(a), "l"(b));
    return d;
}

struct PairSmem {
    __align__(16) u64 geo[Nn * 6];  // per j: (fx,mx),(fy,my),(fz,mz),(np,nm),(fe,fe),pad
    float csum[Nn * 15];    // nllc[c]+nllq[q]+fe^2 per (j, cls*3+chg)
    float colmin[4][Nn];    // per row-group column mins
    float rq[4][Nn];        // per j-quarter row mins
    float red[16];
};
struct SetSmem {
    float  x[SMAX];
    float4 part[300];       // [rc*75 + cg] partial column sums
    float  red[16];
};
union FusedSmem { PairSmem p; SetSmem s; };

// ---------------------------------------------------------------------------
// grid = 256 x 512 threads, occupancy 2. blocks [0,128): pair; [128,256): set.
// Pair loop: f32x2 lanes carry (pos,mom) per row -> both norms in one packed
// chain, 5 LDS/iter (was 7), FMA count unchanged. Set block: float4 column
// loads (75 col-groups x 4 row-chunks) -> 4x fewer LDG issue slots on the
// SMs shared with pair blocks. Last block reduces all partials.
// ---------------------------------------------------------------------------
__global__ void __launch_bounds__(512, 2) fused_kernel(
    const int*   __restrict__ pcls,  const int*   __restrict__ pchg,
    const int*   __restrict__ n_part,
    const float* __restrict__ cl_logits, const float* __restrict__ ch_logits,
    const float* __restrict__ ppos,  const float* __restrict__ fpos,
    const float* __restrict__ pmom,  const float* __restrict__ fmom,
    const float* __restrict__ pe,    const float* __restrict__ fe,
    const float* __restrict__ pred,
    float* __restrict__ out)
{
    __shared__ FusedSmem sm;
    __shared__ unsigned  s_islast;
    __shared__ float     s_fin[8];
    const int t    = threadIdx.x;
    const int lane = t & 31;
    const int w    = t >> 5;

    if (blockIdx.x < Bn) {
        // ================= PAIR-LOSS BLOCK =================
        PairSmem& S = sm.p;
        const int b = blockIdx.x;

        // ---- prologue split across all 512 threads ----
        if (t < Nn) {
            // lower half: NLL tables for pflow j = t
            const int j  = t;
            const int gj = b * Nn + j;
            float nc[5], nq[3];
            {
                const float* cl = cl_logits + gj * 5;
                float x0 = cl[0], x1 = cl[1], x2 = cl[2], x3 = cl[3], x4 = cl[4];
                float m  = fmaxf(fmaxf(fmaxf(x0, x1), fmaxf(x2, x3)), x4);
                float s  = __expf(x0 - m) + __expf(x1 - m) + __expf(x2 - m)
                         + __expf(x3 - m) + __expf(x4 - m);
                float lse = m + __logf(s);
                nc[0] = lse - x0; nc[1] = lse - x1; nc[2] = lse - x2;
                nc[3] = lse - x3; nc[4] = lse - x4;
            }
            {
                const float* ch = ch_logits + gj * 3;
                float x0 = ch[0], x1 = ch[1], x2 = ch[2];
                float m  = fmaxf(fmaxf(x0, x1), x2);
                float s  = __expf(x0 - m) + __expf(x1 - m) + __expf(x2 - m);
                float lse = m + __logf(s);
                nq[0] = lse - x0; nq[1] = lse - x1; nq[2] = lse - x2;
            }
            float fev = fe[gj];
            float fe2 = fev * fev;
            #pragma unroll
            for (int c = 0; c < 5; c++)
                #pragma unroll
                for (int q = 0; q < 3; q++)
                    S.csum[j * 15 + c * 3 + q] = nc[c] + nq[q] + fe2;
        } else {
            // upper half: geometry tables for pflow j = t - 256
            const int j  = t - Nn;
            const int gj = b * Nn + j;
            float fx = fpos[gj * 3 + 0], fy = fpos[gj * 3 + 1], fz = fpos[gj * 3 + 2];
            float mx = fmom[gj * 3 + 0], my = fmom[gj * 3 + 1], mz = fmom[gj * 3 + 2];
            float fev = fe[gj];
            float np  = fmaf(fx, fx, fmaf(fy, fy, fz * fz));
            float nm  = fmaf(mx, mx, fmaf(my, my, mz * mz));
            u64* g = &S.geo[(size_t)j * 6];
            g[0] = pack2(fx, mx);
            g[1] = pack2(fy, my);
            g[2] = pack2(fz, mz);
            g[3] = pack2(np, nm);
            g[4] = pack2(fev, fev);
        }

        // ---- per-thread: two particle rows; (pos,mom) packed per row ----
        const int r   = w & 3;        // row-group: rows [r*64, r*64+64)
        const int q   = w >> 2;       // j-quarter: cols [q*64, q*64+64)
        const int i0  = r * 64 + lane;
        const int i1  = i0 + 32;
        const int gi0 = b * Nn + i0;
        const int gi1 = b * Nn + i1;

        const int cc0 = pcls[gi0] * 3 + pchg[gi0];
        const int cc1 = pcls[gi1] * 3 + pchg[gi1];

        float px0 = ppos[gi0*3+0], py0 = ppos[gi0*3+1], pz0 = ppos[gi0*3+2];
        float qx0 = pmom[gi0*3+0], qy0 = pmom[gi0*3+1], qz0 = pmom[gi0*3+2];
        float pe0v = pe[gi0];
        float px1 = ppos[gi1*3+0], py1 = ppos[gi1*3+1], pz1 = ppos[gi1*3+2];
        float qx1 = pmom[gi1*3+0], qy1 = pmom[gi1*3+1], qz1 = pmom[gi1*3+2];
        float pe1v = pe[gi1];

        // row 0: (pos, mom) packed constants
        const u64 C0x  = pack2(-2.f*px0, -2.f*qx0);
        const u64 C0y  = pack2(-2.f*py0, -2.f*qy0);
        const u64 C0z  = pack2(-2.f*pz0, -2.f*qz0);
        const u64 RPM0 = pack2(fmaf(px0, px0, fmaf(py0, py0, pz0 * pz0)),
                               fmaf(qx0, qx0, fmaf(qy0, qy0, qz0 * qz0)));
        // row 1
        const u64 C1x  = pack2(-2.f*px1, -2.f*qx1);
        const u64 C1y  = pack2(-2.f*py1, -2.f*qy1);
        const u64 C1z  = pack2(-2.f*pz1, -2.f*qz1);
        const u64 RPM1 = pack2(fmaf(px1, px1, fmaf(py1, py1, pz1 * pz1)),
                               fmaf(qx1, qx1, fmaf(qy1, qy1, qz1 * qz1)));
        // energy terms packed (row0, row1)
        const u64 M2E  = pack2(-2.f*pe0v, -2.f*pe1v);
        const u64 PE2  = pack2(pe0v * pe0v, pe1v * pe1v);

        const float* pc0 = S.csum + cc0;
        const float* pc1 = S.csum + cc1;

        __syncthreads();

        // ---- main loop: 5 LDS/iter, both norms per row in one f32x2 chain --
        float rm0a = 1e30f, rm0b = 1e30f, rm1a = 1e30f, rm1b = 1e30f;
        const int jbase = q * 64;
        #pragma unroll 8
        for (int jj = 0; jj < 64; jj++) {
            const int j = jbase + jj;
            const u64* g = &S.geo[(size_t)j * 6];
            ulonglong2 G0 = *reinterpret_cast<const ulonglong2*>(g + 0); // (fx,mx),(fy,my)
            ulonglong2 G1 = *reinterpret_cast<const ulonglong2*>(g + 2); // (fz,mz),(np,nm)
            u64 fe2j = g[4];

            // row 0: d2 = (d2p, d2m) in one packed chain
            u64 d0 = add2(RPM0, G1.y);
            d0 = fma2(C0x, G0.x, d0);
            d0 = fma2(C0y, G0.y, d0);
            d0 = fma2(C0z, G1.x, d0);
            // row 1
            u64 d1 = add2(RPM1, G1.y);
            d1 = fma2(C1x, G0.x, d1);
            d1 = fma2(C1y, G0.y, d1);
            d1 = fma2(C1z, G1.x, d1);

            u64 lb = add2(fma2(M2E, fe2j, pack2(pc0[j * 15], pc1[j * 15])), PE2);

            float dp0, dm0, dp1, dm1, lb0, lb1;
            unpack2(dp0, dm0, d0);
            unpack2(dp1, dm1, d1);
            unpack2(lb0, lb1, lb);

            float l0 = lb0 + (fsqrt_ap(dp0) + fsqrt_ap(dm0));
            float l1 = lb1 + (fsqrt_ap(dp1) + fsqrt_ap(dm1));

            if (jj & 1) { rm0b = fminf(rm0b, l0); rm1b = fminf(rm1b, l1); }
            else        { rm0a = fminf(rm0a, l0); rm1a = fminf(rm1a, l1); }

            float cm = warp_min_nonneg(fminf(l0, l1));
            if (lane == 0) S.colmin[r][j] = cm;
        }
        S.rq[q][i0] = fminf(rm0a, rm0b);
        S.rq[q][i1] = fminf(rm1a, rm1b);
        __syncthreads();

        // ---- combine: sum_i rowmin_i + sum_j colmin_j, block reduce ----
        if (t < Nn) {
            float rm = fminf(fminf(S.rq[0][t], S.rq[1][t]),
                             fminf(S.rq[2][t], S.rq[3][t]));
            float cm = fminf(fminf(S.colmin[0][t], S.colmin[1][t]),
                             fminf(S.colmin[2][t], S.colmin[3][t]));
            float v = rm + cm;
            #pragma unroll
            for (int o = 16; o; o >>= 1) v += __shfl_xor_sync(0xffffffffu, v, o);
            if (lane == 0) S.red[w] = v;
        }
        __syncthreads();
        if (t == 0) {
            float s = 0.f;
            #pragma unroll
            for (int wv = 0; wv < 8; wv++) s += S.red[wv];
            g_partials[b] = s;
        }
    } else {
        // ================= SETSIZE BLOCK (float4, 4x fewer LDG slots) ======
        SetSmem& S = sm.s;
        const int b = blockIdx.x - Bn;
        const float4* base4 = reinterpret_cast<const float4*>(
            pred + (size_t)b * Nn * SMAX);   // row stride = 75 float4

        // threads 0-299: cg = col-group (4 cols), rc = row chunk of 64
        if (t < 300) {
            const int cg = t % 75;
            const int rc = t / 75;
            const float4* p = base4 + (size_t)(rc * 64) * 75 + cg;
            float4 a0 = make_float4(0.f, 0.f, 0.f, 0.f);
            float4 a1 = make_float4(0.f, 0.f, 0.f, 0.f);
            for (int n = 0; n < 64; n += 8) {
                float4 v[8];
                #pragma unroll
                for (int k = 0; k < 8; k++)
                    v[k] = p[(size_t)(n + k) * 75];
                #pragma unroll
                for (int k = 0; k < 8; k += 2) {
                    a0.x += v[k].x;   a0.y += v[k].y;
                    a0.z += v[k].z;   a0.w += v[k].w;
                    a1.x += v[k+1].x; a1.y += v[k+1].y;
                    a1.z += v[k+1].z; a1.w += v[k+1].w;
                }
            }
            a0.x += a1.x; a0.y += a1.y; a0.z += a1.z; a0.w += a1.w;
            S.part[rc * 75 + cg] = a0;
        }
        __syncthreads();
        // threads 0-74: combine 4 row-chunks, write means for 4 columns
        if (t < 75) {
            float4 p0 = S.part[t], p1 = S.part[75 + t];
            float4 p2 = S.part[150 + t], p3 = S.part[225 + t];
            S.x[4 * t + 0] = (p0.x + p1.x + p2.x + p3.x) * (1.f / Nn);
            S.x[4 * t + 1] = (p0.y + p1.y + p2.y + p3.y) * (1.f / Nn);
            S.x[4 * t + 2] = (p0.z + p1.z + p2.z + p3.z) * (1.f / Nn);
            S.x[4 * t + 3] = (p0.w + p1.w + p2.w + p3.w) * (1.f / Nn);
        }
        __syncthreads();

        const bool act = t < SMAX;
        float a = act ? S.x[t] : -1e30f;

        float v = a;
        #pragma unroll
        for (int o = 16; o; o >>= 1) v = fmaxf(v, __shfl_xor_sync(0xffffffffu, v, o));
        if (lane == 0) S.red[w] = v;
        __syncthreads();
        float m = S.red[0];
        #pragma unroll
        for (int wv = 1; wv < 16; wv++) m = fmaxf(m, S.red[wv]);

        float e = act ? __expf(a - m) : 0.f;
        #pragma unroll
        for (int o = 16; o; o >>= 1) e += __shfl_xor_sync(0xffffffffu, e, o);
        __syncthreads();
        if (lane == 0) S.red[w] = e;
        __syncthreads();

        if (t == 0) {
            float Z = 0.f;
            #pragma unroll
            for (int wv = 0; wv < 16; wv++) Z += S.red[wv];
            float logZ = m + __logf(Z);
            g_partials[Bn + b] = logZ - S.x[n_part[b]];
        }
    }

    // ================= COMPLETION-COUNTER FINAL REDUCTION =================
    if (t == 0) {
        __threadfence();
        unsigned old = atomicAdd(&g_count, 1u);
        s_islast = (old == 2u * Bn - 1u) ? 1u : 0u;
    }
    __syncthreads();
    if (s_islast) {
        if (t < 2 * Bn) {
            float v = ((volatile float*)g_partials)[t];
            #pragma unroll
            for (int o = 16; o; o >>= 1) v += __shfl_xor_sync(0xffffffffu, v, o);
            if (lane == 0) s_fin[w] = v;
        }
        __syncthreads();
        if (t == 0) {
            float s = 0.f;
            #pragma unroll
            for (int wv = 0; wv < 8; wv++) s += s_fin[wv];
            out[0] = s * (1.0f / Bn);
            g_count = 0;   // reset for next graph replay
        }
    }
}

extern "C" void kernel_launch(void* const* d_in, const int* in_sizes, int n_in,
                              void* d_out, int out_size)
{
    const int*   pcls  = (const int*)  d_in[0];
    const int*   pchg  = (const int*)  d_in[1];
    const int*   npart = (const int*)  d_in[2];
    const float* cl    = (const float*)d_in[3];
    const float* ch    = (const float*)d_in[4];
    const float* ppos  = (const float*)d_in[5];
    const float* fpos  = (const float*)d_in[6];
    const float* pmom  = (const float*)d_in[7];
    const float* fmom  = (const float*)d_in[8];
    const float* pe    = (const float*)d_in[9];
    const float* fe    = (const float*)d_in[10];
    const float* pred  = (const float*)d_in[11];

    fused_kernel<<<2 * Bn, 512>>>(pcls, pchg, npart, cl, ch,
                                  ppos, fpos, pmom, fmom, pe, fe, pred,
                                  (float*)d_out);
}